// round 15
// baseline (speedup 1.0000x reference)
#include <cuda_runtime.h>
#include <cuda_bf16.h>
#include <math_constants.h>
#include <cstdint>

#define BB    64
#define TT    2048
#define DRNN  1024
#define DEMB  512
#define DATT  128
#define NF    32
#define KS    31
#define PADW  15
#define NSPLIT 32

#define KPAD   104
#define ROWB   208

// ---- energy kernel dynamic smem layout (bytes) ----
#define SM_B     0                         // Wd image: 128 x 208 B
#define SM_LOCB  26624                     // loc bf16: 128 x 208 B
#define SM_AW    53248                     // 2*160 floats
#define SM_CW    54528                     // 62*32 floats
#define SM_PQ    62464                     // 128 floats
#define SM_WV    62976                     // 128 floats
#define SM_E     63488                     // 128 floats
#define SM_TOTAL 64000

// ---------------- device scratch ----------------
__device__ float  g_pq[BB * DATT];
__device__ float2 g_cw2[62 * 16];
__device__ unsigned short g_wdbp[128 * KPAD];  // B image [a][k] bf16: Wh|Wh|Wl|0pad
__device__ float  g_wun[BB * TT];              // unnormalized softmax weights
__device__ float  g_esum[BB * 16];             // per-(b, t-block) partial exp sums
__device__ float  g_ctx_part[NSPLIT * BB * DEMB];

typedef unsigned long long ull;

// ---------------- helpers ----------------
__device__ __forceinline__ ull ffma2u(ull a, ull b, ull c) {
    ull d;
    asm("fma.rn.f32x2 %0, %1, %2, %3;" : "=l"(d) : "l"(a), "l"(b), "l"(c));
    return d;
}
__device__ __forceinline__ ull pack2(float x, float y) {
    ull r; asm("mov.b64 %0, {%1, %2};" : "=l"(r) : "f"(x), "f"(y)); return r;
}
__device__ __forceinline__ float2 unpack2(ull v) {
    float2 f; asm("mov.b64 {%0, %1}, %2;" : "=f"(f.x), "=f"(f.y) : "l"(v)); return f;
}
__device__ __forceinline__ float tanh_fast(float x) {
    float y; asm("tanh.approx.f32 %0, %1;" : "=f"(y) : "f"(x)); return y;
}
__device__ __forceinline__ uint32_t smem_u32(const void* p) {
    uint32_t a;
    asm("{ .reg .u64 t; cvta.to.shared.u64 t, %1; cvt.u32.u64 %0, t; }" : "=r"(a) : "l"(p));
    return a;
}
__device__ __forceinline__ void ldsm4(uint32_t* r, uint32_t addr) {
    asm volatile("ldmatrix.sync.aligned.m8n8.x4.shared.b16 {%0,%1,%2,%3}, [%4];"
        : "=r"(r[0]), "=r"(r[1]), "=r"(r[2]), "=r"(r[3]) : "r"(addr));
}
__device__ __forceinline__ void mma_bf16(float* d, const uint32_t* a,
                                         uint32_t b0, uint32_t b1) {
    asm volatile("mma.sync.aligned.m16n8k16.row.col.f32.bf16.bf16.f32 "
        "{%0,%1,%2,%3}, {%4,%5,%6,%7}, {%8,%9}, {%0,%1,%2,%3};"
        : "+f"(d[0]), "+f"(d[1]), "+f"(d[2]), "+f"(d[3])
        : "r"(a[0]), "r"(a[1]), "r"(a[2]), "r"(a[3]), "r"(b0), "r"(b1));
}

// ---------------- K0: pq GEMM (16x parallel) + conv repack + Wd bf16 image ----------------
__global__ __launch_bounds__(128) void prep_kernel(
    const float* __restrict__ hidden, const float* __restrict__ Wq,
    const float* __restrict__ convw,  const float* __restrict__ Wd)
{
    __shared__ float s_h[DRNN];
    int tid = threadIdx.x, b = blockIdx.x, slice = blockIdx.y;
    for (int i = tid; i < DRNN; i += 128) s_h[i] = hidden[(size_t)b * DRNN + i];
    __syncthreads();

    int w = tid >> 5, lane = tid & 31;
    int a0 = slice * 8 + w * 2;
    const float* wq0 = Wq + (size_t)a0 * DRNN;
    const float* wq1 = wq0 + DRNN;
    float a00 = 0.f, a01 = 0.f, a10 = 0.f, a11 = 0.f;
    #pragma unroll 4
    for (int k = lane; k < DRNN; k += 64) {
        float h0 = s_h[k], h1 = s_h[k + 32];
        a00 = fmaf(h0, wq0[k],      a00);
        a01 = fmaf(h1, wq0[k + 32], a01);
        a10 = fmaf(h0, wq1[k],      a10);
        a11 = fmaf(h1, wq1[k + 32], a11);
    }
    float rA = a00 + a01, rB = a10 + a11;
    #pragma unroll
    for (int off = 16; off; off >>= 1) {
        rA += __shfl_down_sync(0xffffffffu, rA, off);
        rB += __shfl_down_sync(0xffffffffu, rB, off);
    }
    if (lane == 0) {
        g_pq[b * DATT + a0]     = rA;
        g_pq[b * DATT + a0 + 1] = rB;
    }

    if (b == 0 && slice == 0) {
        for (int i = tid; i < 62 * 16; i += 128) {
            int ck = i >> 4, fp = i & 15;
            g_cw2[i] = make_float2(convw[(2 * fp) * 62 + ck], convw[(2 * fp + 1) * 62 + ck]);
        }
    }
    if (b == 1 && slice == 0) {
        int a = tid;
        if (a < 128) {
            const float* wrow = Wd + a * NF;
            unsigned short* orow = g_wdbp + a * KPAD;
            #pragma unroll 4
            for (int k = 0; k < KPAD; k++) {
                __nv_bfloat16 bv = __float2bfloat16(0.f);
                if (k < 64) {
                    bv = __float2bfloat16(wrow[k & 31]);
                } else if (k < 96) {
                    float orig = wrow[k - 64];
                    float hi = __bfloat162float(__float2bfloat16(orig));
                    bv = __float2bfloat16(orig - hi);
                }
                orow[k] = *(unsigned short*)&bv;
            }
        }
    }
}

__global__ void dummy_kernel() {}

// ---------------- K1: conv + mma.sync paw + tanh + v-dot + mask/exp -> unnorm weights ----------------
__global__ __launch_bounds__(256) void energy_kernel(
    const float* __restrict__ pm, const float* __restrict__ aw,
    const float* __restrict__ wv, const int* __restrict__ mask)
{
    extern __shared__ __align__(16) char smc[];
    float* s_aw = (float*)(smc + SM_AW);
    float* s_cw = (float*)(smc + SM_CW);
    float* s_pq = (float*)(smc + SM_PQ);
    float* s_wv = (float*)(smc + SM_WV);
    float* s_e  = (float*)(smc + SM_E);

    int tid = threadIdx.x;
    int b   = blockIdx.y;
    int t0  = blockIdx.x * 128;
    int w   = tid >> 5, lane = tid & 31;
    uint32_t sbase = smem_u32(smc);

    // ---- stage: B image, conv inputs, pq, wv ----
    {
        const float4* src = (const float4*)g_wdbp;     // 1664 float4
        float4* dst = (float4*)(smc + SM_B);
        for (int i = tid; i < 1664; i += 256) dst[i] = src[i];
    }
    const float* awB = aw + (size_t)b * 2 * TT;
    for (int i = tid; i < 2 * 158; i += 256) {
        int c = i / 158, j = i - c * 158;
        int tg = t0 + j - PADW;
        s_aw[c * 160 + j] = (tg >= 0 && tg < TT) ? awB[(size_t)c * TT + tg] : 0.f;
    }
    {
        const float4* src = (const float4*)g_cw2;      // 496 float4
        float4* dst = (float4*)s_cw;
        for (int i = tid; i < 496; i += 256) dst[i] = src[i];
    }
    if (tid < 128) {
        s_pq[tid] = g_pq[b * DATT + tid];
        s_wv[tid] = wv[tid];
    }
    __syncthreads();

    // ---- conv: thread (tloc = tid&127, fh = tid>>7) -> loc[t][16 filters] ----
    {
        const int tloc = tid & 127, fh = tid >> 7;
        ull cacc[8];
        #pragma unroll
        for (int i = 0; i < 8; i++) cacc[i] = 0ULL;
        #pragma unroll 2
        for (int ck = 0; ck < 62; ck++) {
            int c = (ck >= 31), k = ck - c * 31;
            float av = s_aw[c * 160 + tloc + k];
            ull av2 = pack2(av, av);
            const ulonglong2* row = (const ulonglong2*)(s_cw + ck * 32 + fh * 16);
            #pragma unroll
            for (int q = 0; q < 4; q++) {
                ulonglong2 w2 = row[q];
                cacc[2 * q]     = ffma2u(av2, w2.x, cacc[2 * q]);
                cacc[2 * q + 1] = ffma2u(av2, w2.y, cacc[2 * q + 1]);
            }
        }
        uint32_t awords[24];
        #pragma unroll
        for (int fp = 0; fp < 8; fp++) {
            float2 v = unpack2(cacc[fp]);
            __nv_bfloat16 h0 = __float2bfloat16(v.x), h1 = __float2bfloat16(v.y);
            float r0 = v.x - __bfloat162float(h0);
            float r1 = v.y - __bfloat162float(h1);
            __nv_bfloat16 l0 = __float2bfloat16(r0), l1 = __float2bfloat16(r1);
            uint32_t hw = ((uint32_t)__bfloat16_as_ushort(h1) << 16) | __bfloat16_as_ushort(h0);
            uint32_t lw = ((uint32_t)__bfloat16_as_ushort(l1) << 16) | __bfloat16_as_ushort(l0);
            awords[fp]      = hw;
            awords[8 + fp]  = lw;
            awords[16 + fp] = hw;
        }
        char* base = smc + SM_LOCB + tloc * ROWB + fh * 32;
        #pragma unroll
        for (int sgm = 0; sgm < 3; sgm++) {
            uint4* dst = (uint4*)(base + sgm * 64);
            dst[0] = make_uint4(awords[8 * sgm],     awords[8 * sgm + 1],
                                awords[8 * sgm + 2], awords[8 * sgm + 3]);
            dst[1] = make_uint4(awords[8 * sgm + 4], awords[8 * sgm + 5],
                                awords[8 * sgm + 6], awords[8 * sgm + 7]);
        }
    }
    __syncthreads();

    // ---- per-warp MMA + epilogue (m16 tile rows mb..mb+15) ----
    const int mb = w * 16;
    const uint32_t sLocb = sbase + SM_LOCB;
    const uint32_t sBimg = sbase + SM_B;
    const int r0 = mb + (lane >> 2);
    const float* pr0 = pm + ((size_t)b * TT + t0 + r0) * DATT;
    const float* pr1 = pr0 + 8 * DATT;
    const int ac = 2 * (lane & 3);

    float es0 = 0.f, es1 = 0.f;

    #pragma unroll
    for (int nh = 0; nh < 2; nh++) {
        float2 pv0[8], pv1[8];
        #pragma unroll
        for (int nt = 0; nt < 8; nt++) {
            int a0 = nh * 64 + nt * 8 + ac;
            pv0[nt] = *(const float2*)(pr0 + a0);
            pv1[nt] = *(const float2*)(pr1 + a0);
        }

        float acc[8][4];
        #pragma unroll
        for (int nt = 0; nt < 8; nt++)
            #pragma unroll
            for (int q = 0; q < 4; q++) acc[nt][q] = 0.f;

        #pragma unroll
        for (int ks = 0; ks < 6; ks++) {
            const int kk = ks * 16;
            uint32_t af[4];
            ldsm4(af, sLocb + (mb + (lane & 15)) * ROWB + (kk + (lane >> 4) * 8) * 2);
            uint32_t bf[4][4];
            #pragma unroll
            for (int ng = 0; ng < 4; ng++) {
                uint32_t baddr = sBimg
                    + (nh * 64 + ng * 16 + ((lane >> 4) << 3) + (lane & 7)) * ROWB
                    + (kk + ((lane >> 3) & 1) * 8) * 2;
                ldsm4(bf[ng], baddr);
            }
            #pragma unroll
            for (int ng = 0; ng < 4; ng++) {
                mma_bf16(acc[2 * ng],     af, bf[ng][0], bf[ng][1]);
                mma_bf16(acc[2 * ng + 1], af, bf[ng][2], bf[ng][3]);
            }
        }

        #pragma unroll
        for (int nt = 0; nt < 8; nt++) {
            int a0 = nh * 64 + nt * 8 + ac;
            float2 q = *(const float2*)(s_pq + a0);
            float2 v = *(const float2*)(s_wv + a0);
            const float* c = acc[nt];
            es0 = fmaf(v.x, tanh_fast(c[0] + q.x + pv0[nt].x), es0);
            es0 = fmaf(v.y, tanh_fast(c[1] + q.y + pv0[nt].y), es0);
            es1 = fmaf(v.x, tanh_fast(c[2] + q.x + pv1[nt].x), es1);
            es1 = fmaf(v.y, tanh_fast(c[3] + q.y + pv1[nt].y), es1);
        }
    }

    #pragma unroll
    for (int off = 1; off <= 2; off <<= 1) {
        es0 += __shfl_xor_sync(0xffffffffu, es0, off);
        es1 += __shfl_xor_sync(0xffffffffu, es1, off);
    }
    if ((lane & 3) == 0) {
        s_e[r0]     = es0;
        s_e[r0 + 8] = es1;
    }
    __syncthreads();

    // ---- mask + exp -> unnormalized weights; block partial sum ----
    if (tid < 128) {
        float e = s_e[tid];
        float wu = (mask[(size_t)b * TT + t0 + tid] != 0) ? 0.f : __expf(e);
        g_wun[(size_t)b * TT + t0 + tid] = wu;
        s_e[tid] = wu;
    }
    __syncthreads();
    if (tid < 32) {
        float s = s_e[tid] + s_e[tid + 32] + s_e[tid + 64] + s_e[tid + 96];
        #pragma unroll
        for (int off = 16; off; off >>= 1) s += __shfl_down_sync(0xffffffffu, s, off);
        if (tid == 0) g_esum[b * 16 + blockIdx.x] = s;
    }
}

// ---------------- K3: context partials + weight normalization + out_w ----------------
__global__ __launch_bounds__(128) void context_kernel(
    const float* __restrict__ memory, float* __restrict__ out_w)
{
    __shared__ float s_w[64];
    int tid = threadIdx.x;
    int b = blockIdx.y, ts = blockIdx.x;
    int t0 = ts * 64;

    float tot = 0.f;
    #pragma unroll
    for (int i = 0; i < 16; i++) tot += g_esum[b * 16 + i];
    float inv = 1.f / tot;

    if (tid < 64) {
        float wn = g_wun[(size_t)b * TT + t0 + tid] * inv;
        s_w[tid] = wn;
        out_w[(size_t)b * TT + t0 + tid] = wn;
    }
    __syncthreads();

    const float4* m4 = (const float4*)(memory + ((size_t)b * TT + t0) * DEMB) + tid;
    float4 acc = make_float4(0.f, 0.f, 0.f, 0.f);
    for (int i = 0; i < 64; i += 8) {
        float4 v[8];
        #pragma unroll
        for (int u = 0; u < 8; u++) v[u] = m4[(size_t)(i + u) * 128];
        #pragma unroll
        for (int u = 0; u < 8; u++) {
            float w = s_w[i + u];
            acc.x = fmaf(w, v[u].x, acc.x);
            acc.y = fmaf(w, v[u].y, acc.y);
            acc.z = fmaf(w, v[u].z, acc.z);
            acc.w = fmaf(w, v[u].w, acc.w);
        }
    }
    ((float4*)g_ctx_part)[(size_t)ts * (BB * DEMB / 4) + b * (DEMB / 4) + tid] = acc;
}

// ---------------- K4: reduce context partials (float4, 128 blocks x 64 thr) ----------------
__global__ __launch_bounds__(64) void reduce_kernel(float* __restrict__ out_ctx)
{
    int i = blockIdx.x * 64 + threadIdx.x;     // 8192 float4 outputs
    const float4* p = (const float4*)g_ctx_part;
    float4 s = make_float4(0.f, 0.f, 0.f, 0.f);
    #pragma unroll
    for (int ts = 0; ts < NSPLIT; ts++) {
        float4 v = p[(size_t)ts * 8192 + i];
        s.x += v.x; s.y += v.y; s.z += v.z; s.w += v.w;
    }
    ((float4*)out_ctx)[i] = s;
}

// ---------------- launch ----------------
// 3 dummies first: the ncu capture slot lands on the 4th launch = prep_kernel
// (finally measuring prep directly).
extern "C" void kernel_launch(void* const* d_in, const int* in_sizes, int n_in,
                              void* d_out, int out_size)
{
    const float* hidden = (const float*)d_in[0];
    const float* memory = (const float*)d_in[1];
    const float* pm     = (const float*)d_in[2];
    const float* awc    = (const float*)d_in[3];
    const int*   mask   = (const int*)d_in[4];
    const float* Wq     = (const float*)d_in[5];
    const float* Wv     = (const float*)d_in[6];
    const float* convw  = (const float*)d_in[7];
    const float* Wd     = (const float*)d_in[8];

    float* out     = (float*)d_out;
    float* out_ctx = out;                  // [B, 512]
    float* out_w   = out + BB * DEMB;      // [B, T]

    cudaFuncSetAttribute(energy_kernel,
                         cudaFuncAttributeMaxDynamicSharedMemorySize, SM_TOTAL);

    dummy_kernel<<<1, 32>>>();
    dummy_kernel<<<1, 32>>>();
    dummy_kernel<<<1, 32>>>();
    prep_kernel<<<dim3(64, 16), 128>>>(hidden, Wq, convw, Wd);
    energy_kernel<<<dim3(16, 64), 256, SM_TOTAL>>>(pm, awc, Wv, mask);
    context_kernel<<<dim3(NSPLIT, 64), 128>>>(memory, out_w);
    reduce_kernel<<<128, 64>>>(out_ctx);
}

// round 16
// speedup vs baseline: 1.3259x; 1.3259x over previous
#include <cuda_runtime.h>
#include <cuda_bf16.h>
#include <math_constants.h>
#include <cstdint>

#define BB    64
#define TT    2048
#define DRNN  1024
#define DEMB  512
#define DATT  128
#define NF    32
#define KS    31
#define PADW  15
#define NSPLIT 32

#define KPAD   104
#define ROWB   208

// ---- energy kernel dynamic smem layout (bytes) ----
#define SM_B     0                         // Wd image: 128 x 208 B
#define SM_LOCB  26624                     // loc bf16: 128 x 208 B
#define SM_AW    53248                     // 2*160 floats
#define SM_CW    54528                     // 62*32 floats
#define SM_PQ    62464                     // 128 floats
#define SM_WV    62976                     // 128 floats
#define SM_E     63488                     // 128 floats
#define SM_TOTAL 64000

// ---------------- device scratch ----------------
__device__ float  g_pq[BB * DATT];
__device__ float2 g_cw2[62 * 16];
__device__ unsigned short g_wdbp[128 * KPAD];  // B image [a][k] bf16: Wh|Wh|Wl|0pad
__device__ float  g_wun[BB * TT];              // unnormalized softmax weights
__device__ float  g_esum[BB * 16];             // per-(b, t-block) partial exp sums
__device__ float  g_ctx_part[NSPLIT * BB * DEMB];

typedef unsigned long long ull;

// ---------------- helpers ----------------
__device__ __forceinline__ ull ffma2u(ull a, ull b, ull c) {
    ull d;
    asm("fma.rn.f32x2 %0, %1, %2, %3;" : "=l"(d) : "l"(a), "l"(b), "l"(c));
    return d;
}
__device__ __forceinline__ ull pack2(float x, float y) {
    ull r; asm("mov.b64 %0, {%1, %2};" : "=l"(r) : "f"(x), "f"(y)); return r;
}
__device__ __forceinline__ float2 unpack2(ull v) {
    float2 f; asm("mov.b64 {%0, %1}, %2;" : "=f"(f.x), "=f"(f.y) : "l"(v)); return f;
}
__device__ __forceinline__ float tanh_fast(float x) {
    float y; asm("tanh.approx.f32 %0, %1;" : "=f"(y) : "f"(x)); return y;
}
__device__ __forceinline__ uint32_t smem_u32(const void* p) {
    uint32_t a;
    asm("{ .reg .u64 t; cvta.to.shared.u64 t, %1; cvt.u32.u64 %0, t; }" : "=r"(a) : "l"(p));
    return a;
}
__device__ __forceinline__ void ldsm4(uint32_t* r, uint32_t addr) {
    asm volatile("ldmatrix.sync.aligned.m8n8.x4.shared.b16 {%0,%1,%2,%3}, [%4];"
        : "=r"(r[0]), "=r"(r[1]), "=r"(r[2]), "=r"(r[3]) : "r"(addr));
}
__device__ __forceinline__ void mma_bf16(float* d, const uint32_t* a,
                                         uint32_t b0, uint32_t b1) {
    asm volatile("mma.sync.aligned.m16n8k16.row.col.f32.bf16.bf16.f32 "
        "{%0,%1,%2,%3}, {%4,%5,%6,%7}, {%8,%9}, {%0,%1,%2,%3};"
        : "+f"(d[0]), "+f"(d[1]), "+f"(d[2]), "+f"(d[3])
        : "r"(a[0]), "r"(a[1]), "r"(a[2]), "r"(a[3]), "r"(b0), "r"(b1));
}

// ---------------- K0: pq GEMV (float4, MLP=16) + parallel repack tails ----------------
// grid (64, 16). Block (b, slice): warp computes 2 a-rows, fully unrolled float4 loads.
// Repack work parallelized: conv repack over b==0 slices, Wd image over b==1 slices.
__global__ __launch_bounds__(128) void prep_kernel(
    const float* __restrict__ hidden, const float* __restrict__ Wq,
    const float* __restrict__ convw,  const float* __restrict__ Wd)
{
    __shared__ float4 s_h4[256];
    int tid = threadIdx.x, b = blockIdx.x, slice = blockIdx.y;
    {
        const float4* h4 = (const float4*)(hidden + (size_t)b * DRNN);
        s_h4[tid]       = h4[tid];
        s_h4[tid + 128] = h4[tid + 128];
    }
    __syncthreads();

    int w = tid >> 5, lane = tid & 31;
    int a0 = slice * 8 + w * 2;
    const float4* wq0 = (const float4*)(Wq + (size_t)a0 * DRNN);
    const float4* wq1 = wq0 + 256;
    float4 acc0 = make_float4(0.f, 0.f, 0.f, 0.f);
    float4 acc1 = make_float4(0.f, 0.f, 0.f, 0.f);
    #pragma unroll
    for (int j = 0; j < 8; j++) {
        int k = lane + j * 32;
        float4 h  = s_h4[k];
        float4 w0 = wq0[k];
        float4 w1 = wq1[k];
        acc0.x = fmaf(h.x, w0.x, acc0.x); acc0.y = fmaf(h.y, w0.y, acc0.y);
        acc0.z = fmaf(h.z, w0.z, acc0.z); acc0.w = fmaf(h.w, w0.w, acc0.w);
        acc1.x = fmaf(h.x, w1.x, acc1.x); acc1.y = fmaf(h.y, w1.y, acc1.y);
        acc1.z = fmaf(h.z, w1.z, acc1.z); acc1.w = fmaf(h.w, w1.w, acc1.w);
    }
    float rA = (acc0.x + acc0.y) + (acc0.z + acc0.w);
    float rB = (acc1.x + acc1.y) + (acc1.z + acc1.w);
    #pragma unroll
    for (int off = 16; off; off >>= 1) {
        rA += __shfl_down_sync(0xffffffffu, rA, off);
        rB += __shfl_down_sync(0xffffffffu, rB, off);
    }
    if (lane == 0) {
        g_pq[b * DATT + a0]     = rA;
        g_pq[b * DATT + a0 + 1] = rB;
    }

    // conv repack: slice s of b==0 handles 62 elements (i = s*62 + t)
    if (b == 0 && tid < 62) {
        int i = slice * 62 + tid;
        if (i < 62 * 16) {
            int ck = i >> 4, fp = i & 15;
            g_cw2[i] = make_float2(convw[(2 * fp) * 62 + ck], convw[(2 * fp + 1) * 62 + ck]);
        }
    }
    // Wd image: slice s of b==1 handles rows a = s*8 .. s*8+7 (16 threads/row)
    if (b == 1) {
        int a = slice * 8 + (tid >> 4);
        int kb = tid & 15;
        const float* wrow = Wd + a * NF;
        unsigned short* orow = g_wdbp + a * KPAD;
        #pragma unroll
        for (int j = 0; j < 7; j++) {
            int k = kb + j * 16;
            if (k < KPAD) {
                __nv_bfloat16 bv = __float2bfloat16(0.f);
                if (k < 64) {
                    bv = __float2bfloat16(wrow[k & 31]);
                } else if (k < 96) {
                    float orig = wrow[k - 64];
                    float hi = __bfloat162float(__float2bfloat16(orig));
                    bv = __float2bfloat16(orig - hi);
                }
                orow[k] = *(unsigned short*)&bv;
            }
        }
    }
}

// ---------------- K1: conv + mma.sync paw + tanh + v-dot + mask/exp -> unnorm weights ----------------
__global__ __launch_bounds__(256) void energy_kernel(
    const float* __restrict__ pm, const float* __restrict__ aw,
    const float* __restrict__ wv, const int* __restrict__ mask)
{
    extern __shared__ __align__(16) char smc[];
    float* s_aw = (float*)(smc + SM_AW);
    float* s_cw = (float*)(smc + SM_CW);
    float* s_pq = (float*)(smc + SM_PQ);
    float* s_wv = (float*)(smc + SM_WV);
    float* s_e  = (float*)(smc + SM_E);

    int tid = threadIdx.x;
    int b   = blockIdx.y;
    int t0  = blockIdx.x * 128;
    int w   = tid >> 5, lane = tid & 31;
    uint32_t sbase = smem_u32(smc);

    {
        const float4* src = (const float4*)g_wdbp;     // 1664 float4
        float4* dst = (float4*)(smc + SM_B);
        for (int i = tid; i < 1664; i += 256) dst[i] = src[i];
    }
    const float* awB = aw + (size_t)b * 2 * TT;
    for (int i = tid; i < 2 * 158; i += 256) {
        int c = i / 158, j = i - c * 158;
        int tg = t0 + j - PADW;
        s_aw[c * 160 + j] = (tg >= 0 && tg < TT) ? awB[(size_t)c * TT + tg] : 0.f;
    }
    {
        const float4* src = (const float4*)g_cw2;      // 496 float4
        float4* dst = (float4*)s_cw;
        for (int i = tid; i < 496; i += 256) dst[i] = src[i];
    }
    if (tid < 128) {
        s_pq[tid] = g_pq[b * DATT + tid];
        s_wv[tid] = wv[tid];
    }
    __syncthreads();

    // ---- conv: thread (tloc = tid&127, fh = tid>>7) -> loc[t][16 filters] ----
    {
        const int tloc = tid & 127, fh = tid >> 7;
        ull cacc[8];
        #pragma unroll
        for (int i = 0; i < 8; i++) cacc[i] = 0ULL;
        #pragma unroll 2
        for (int ck = 0; ck < 62; ck++) {
            int c = (ck >= 31), k = ck - c * 31;
            float av = s_aw[c * 160 + tloc + k];
            ull av2 = pack2(av, av);
            const ulonglong2* row = (const ulonglong2*)(s_cw + ck * 32 + fh * 16);
            #pragma unroll
            for (int q = 0; q < 4; q++) {
                ulonglong2 w2 = row[q];
                cacc[2 * q]     = ffma2u(av2, w2.x, cacc[2 * q]);
                cacc[2 * q + 1] = ffma2u(av2, w2.y, cacc[2 * q + 1]);
            }
        }
        uint32_t awords[24];
        #pragma unroll
        for (int fp = 0; fp < 8; fp++) {
            float2 v = unpack2(cacc[fp]);
            __nv_bfloat16 h0 = __float2bfloat16(v.x), h1 = __float2bfloat16(v.y);
            float r0 = v.x - __bfloat162float(h0);
            float r1 = v.y - __bfloat162float(h1);
            __nv_bfloat16 l0 = __float2bfloat16(r0), l1 = __float2bfloat16(r1);
            uint32_t hw = ((uint32_t)__bfloat16_as_ushort(h1) << 16) | __bfloat16_as_ushort(h0);
            uint32_t lw = ((uint32_t)__bfloat16_as_ushort(l1) << 16) | __bfloat16_as_ushort(l0);
            awords[fp]      = hw;
            awords[8 + fp]  = lw;
            awords[16 + fp] = hw;
        }
        char* base = smc + SM_LOCB + tloc * ROWB + fh * 32;
        #pragma unroll
        for (int sgm = 0; sgm < 3; sgm++) {
            uint4* dst = (uint4*)(base + sgm * 64);
            dst[0] = make_uint4(awords[8 * sgm],     awords[8 * sgm + 1],
                                awords[8 * sgm + 2], awords[8 * sgm + 3]);
            dst[1] = make_uint4(awords[8 * sgm + 4], awords[8 * sgm + 5],
                                awords[8 * sgm + 6], awords[8 * sgm + 7]);
        }
    }
    __syncthreads();

    // ---- per-warp MMA + epilogue (m16 tile rows mb..mb+15) ----
    const int mb = w * 16;
    const uint32_t sLocb = sbase + SM_LOCB;
    const uint32_t sBimg = sbase + SM_B;
    const int r0 = mb + (lane >> 2);
    const float* pr0 = pm + ((size_t)b * TT + t0 + r0) * DATT;
    const float* pr1 = pr0 + 8 * DATT;
    const int ac = 2 * (lane & 3);

    float es0 = 0.f, es1 = 0.f;

    #pragma unroll
    for (int nh = 0; nh < 2; nh++) {
        float2 pv0[8], pv1[8];
        #pragma unroll
        for (int nt = 0; nt < 8; nt++) {
            int a0 = nh * 64 + nt * 8 + ac;
            pv0[nt] = *(const float2*)(pr0 + a0);
            pv1[nt] = *(const float2*)(pr1 + a0);
        }

        float acc[8][4];
        #pragma unroll
        for (int nt = 0; nt < 8; nt++)
            #pragma unroll
            for (int q = 0; q < 4; q++) acc[nt][q] = 0.f;

        #pragma unroll
        for (int ks = 0; ks < 6; ks++) {
            const int kk = ks * 16;
            uint32_t af[4];
            ldsm4(af, sLocb + (mb + (lane & 15)) * ROWB + (kk + (lane >> 4) * 8) * 2);
            uint32_t bf[4][4];
            #pragma unroll
            for (int ng = 0; ng < 4; ng++) {
                uint32_t baddr = sBimg
                    + (nh * 64 + ng * 16 + ((lane >> 4) << 3) + (lane & 7)) * ROWB
                    + (kk + ((lane >> 3) & 1) * 8) * 2;
                ldsm4(bf[ng], baddr);
            }
            #pragma unroll
            for (int ng = 0; ng < 4; ng++) {
                mma_bf16(acc[2 * ng],     af, bf[ng][0], bf[ng][1]);
                mma_bf16(acc[2 * ng + 1], af, bf[ng][2], bf[ng][3]);
            }
        }

        #pragma unroll
        for (int nt = 0; nt < 8; nt++) {
            int a0 = nh * 64 + nt * 8 + ac;
            float2 q = *(const float2*)(s_pq + a0);
            float2 v = *(const float2*)(s_wv + a0);
            const float* c = acc[nt];
            es0 = fmaf(v.x, tanh_fast(c[0] + q.x + pv0[nt].x), es0);
            es0 = fmaf(v.y, tanh_fast(c[1] + q.y + pv0[nt].y), es0);
            es1 = fmaf(v.x, tanh_fast(c[2] + q.x + pv1[nt].x), es1);
            es1 = fmaf(v.y, tanh_fast(c[3] + q.y + pv1[nt].y), es1);
        }
    }

    #pragma unroll
    for (int off = 1; off <= 2; off <<= 1) {
        es0 += __shfl_xor_sync(0xffffffffu, es0, off);
        es1 += __shfl_xor_sync(0xffffffffu, es1, off);
    }
    if ((lane & 3) == 0) {
        s_e[r0]     = es0;
        s_e[r0 + 8] = es1;
    }
    __syncthreads();

    // ---- mask + exp -> unnormalized weights; block partial sum ----
    if (tid < 128) {
        float e = s_e[tid];
        float wu = (mask[(size_t)b * TT + t0 + tid] != 0) ? 0.f : __expf(e);
        g_wun[(size_t)b * TT + t0 + tid] = wu;
        s_e[tid] = wu;
    }
    __syncthreads();
    if (tid < 32) {
        float s = s_e[tid] + s_e[tid + 32] + s_e[tid + 64] + s_e[tid + 96];
        #pragma unroll
        for (int off = 16; off; off >>= 1) s += __shfl_down_sync(0xffffffffu, s, off);
        if (tid == 0) g_esum[b * 16 + blockIdx.x] = s;
    }
}

// ---------------- K3: context partials + weight normalization + out_w ----------------
__global__ __launch_bounds__(128) void context_kernel(
    const float* __restrict__ memory, float* __restrict__ out_w)
{
    __shared__ float s_w[64];
    int tid = threadIdx.x;
    int b = blockIdx.y, ts = blockIdx.x;
    int t0 = ts * 64;

    float tot = 0.f;
    #pragma unroll
    for (int i = 0; i < 16; i++) tot += g_esum[b * 16 + i];
    float inv = 1.f / tot;

    if (tid < 64) {
        float wn = g_wun[(size_t)b * TT + t0 + tid] * inv;
        s_w[tid] = wn;
        out_w[(size_t)b * TT + t0 + tid] = wn;
    }
    __syncthreads();

    const float4* m4 = (const float4*)(memory + ((size_t)b * TT + t0) * DEMB) + tid;
    float4 acc = make_float4(0.f, 0.f, 0.f, 0.f);
    for (int i = 0; i < 64; i += 8) {
        float4 v[8];
        #pragma unroll
        for (int u = 0; u < 8; u++) v[u] = m4[(size_t)(i + u) * 128];
        #pragma unroll
        for (int u = 0; u < 8; u++) {
            float w = s_w[i + u];
            acc.x = fmaf(w, v[u].x, acc.x);
            acc.y = fmaf(w, v[u].y, acc.y);
            acc.z = fmaf(w, v[u].z, acc.z);
            acc.w = fmaf(w, v[u].w, acc.w);
        }
    }
    ((float4*)g_ctx_part)[(size_t)ts * (BB * DEMB / 4) + b * (DEMB / 4) + tid] = acc;
}

// ---------------- K4: reduce context partials (float4) ----------------
__global__ __launch_bounds__(64) void reduce_kernel(float* __restrict__ out_ctx)
{
    int i = blockIdx.x * 64 + threadIdx.x;     // 8192 float4 outputs
    const float4* p = (const float4*)g_ctx_part;
    float4 s = make_float4(0.f, 0.f, 0.f, 0.f);
    #pragma unroll
    for (int ts = 0; ts < NSPLIT; ts++) {
        float4 v = p[(size_t)ts * 8192 + i];
        s.x += v.x; s.y += v.y; s.z += v.z; s.w += v.w;
    }
    ((float4*)out_ctx)[i] = s;
}

// ---------------- launch (4 kernels, no dummies) ----------------
extern "C" void kernel_launch(void* const* d_in, const int* in_sizes, int n_in,
                              void* d_out, int out_size)
{
    const float* hidden = (const float*)d_in[0];
    const float* memory = (const float*)d_in[1];
    const float* pm     = (const float*)d_in[2];
    const float* awc    = (const float*)d_in[3];
    const int*   mask   = (const int*)d_in[4];
    const float* Wq     = (const float*)d_in[5];
    const float* Wv     = (const float*)d_in[6];
    const float* convw  = (const float*)d_in[7];
    const float* Wd     = (const float*)d_in[8];

    float* out     = (float*)d_out;
    float* out_ctx = out;                  // [B, 512]
    float* out_w   = out + BB * DEMB;      // [B, T]

    cudaFuncSetAttribute(energy_kernel,
                         cudaFuncAttributeMaxDynamicSharedMemorySize, SM_TOTAL);

    prep_kernel<<<dim3(64, 16), 128>>>(hidden, Wq, convw, Wd);
    energy_kernel<<<dim3(16, 64), 256, SM_TOTAL>>>(pm, awc, Wv, mask);
    context_kernel<<<dim3(NSPLIT, 64), 128>>>(memory, out_w);
    reduce_kernel<<<128, 64>>>(out_ctx);
}